// round 14
// baseline (speedup 1.0000x reference)
#include <cuda_runtime.h>

// inputs: [128, 65536, 3] f32 interleaved (x,y,z)
// output: [128, 65536, 2] f32: (-(clip(x,-1,1)+1)*90, atan2(z,y)*180/pi)
//
// psi = acos(y/sqrt(y^2+z^2)) with sign of z  ==  atan2(z, y)
//
// Persistent grid-stride variant of the best (R3) kernel: identical
// per-iteration memory shape (3x strided LDG.128 in, 2x STG.128 out),
// but a single wave of 148*8 CTAs looping ~7 times removes wave-transition
// overhead and lets ptxas overlap next-iter loads with current stores.

#define TPB 256

static __device__ __forceinline__ float fast_atan2_deg(float z, float y) {
    // atan2(z,y) * (180/pi), minimax atan poly on [0,1], max err ~1e-5 rad
    float ay = fabsf(y), az = fabsf(z);
    float mn = fminf(ay, az), mx = fmaxf(ay, az);
    float a = __fdividef(mn, mx);
    float s = a * a;
    float r = fmaf(fmaf(fmaf(fmaf(0.0208351f, s, -0.0851330f),
                             s, 0.1801410f),
                        s, -0.3302995f),
                   s, 0.9998660f) * a;
    if (az > ay) r = 1.5707963267948966f - r;
    if (y < 0.0f) r = 3.14159265358979323f - r;
    r = (z < 0.0f) ? -r : r;
    return r * 57.295779513082323f;
}

static __device__ __forceinline__ void point_op(float x, float y, float z,
                                                float& o0, float& o1) {
    float cx = fminf(fmaxf(x, -1.0f), 1.0f);
    o0 = fmaf(cx, -90.0f, -90.0f);   // -(cx+1)*90
    o1 = fast_atan2_deg(z, y);
}

__global__ void __launch_bounds__(TPB) cil_kernel(const float4* __restrict__ in4,
                                                  float4* __restrict__ out4,
                                                  int n_quads) {
    int stride = gridDim.x * TPB;
    for (int t = blockIdx.x * TPB + threadIdx.x; t < n_quads; t += stride) {
        // 4 points = 12 floats in = 3x LDG.128 ; 8 floats out = 2x STG.128
        float4 a = in4[3 * t + 0];  // x0 y0 z0 x1
        float4 b = in4[3 * t + 1];  // y1 z1 x2 y2
        float4 c = in4[3 * t + 2];  // z2 x3 y3 z3

        float4 o0, o1;
        point_op(a.x, a.y, a.z, o0.x, o0.y);  // p0
        point_op(a.w, b.x, b.y, o0.z, o0.w);  // p1
        point_op(b.z, b.w, c.x, o1.x, o1.y);  // p2
        point_op(c.y, c.z, c.w, o1.z, o1.w);  // p3

        out4[2 * t + 0] = o0;
        out4[2 * t + 1] = o1;
    }
}

extern "C" void kernel_launch(void* const* d_in, const int* in_sizes, int n_in,
                              void* d_out, int out_size) {
    const float4* in4 = (const float4*)d_in[0];
    float4* out4 = (float4*)d_out;

    int n_points = in_sizes[0] / 3;      // 8,388,608
    int n_quads = n_points / 4;          // 2,097,152 (exact: divisible)

    int grid = 148 * 8;                  // one full wave at occ 8 CTAs/SM
    cil_kernel<<<grid, TPB>>>(in4, out4, n_quads);
}

// round 16
// speedup vs baseline: 1.2267x; 1.2267x over previous
#include <cuda_runtime.h>

// inputs: [128, 65536, 3] f32 interleaved (x,y,z)
// output: [128, 65536, 2] f32: (-(clip(x,-1,1)+1)*90, atan2(z,y)*180/pi)
//
// psi = acos(y/sqrt(y^2+z^2)) with sign of z  ==  atan2(z, y)
//
// Final form: 4 points/thread, 3x LDG.128 in, 2x STG.128 out, cheap
// predicated minimax atan2. Empirically at the mixed r/w HBM ceiling
// (7.5 TB/s wall-clock); all structural alternatives (cp.async pipeline,
// smem coalescing, v8.b32, persistent loop, higher MLP) measured slower.

#define TPB 256

static __device__ __forceinline__ float fast_atan2_deg(float z, float y) {
    // atan2(z,y) * (180/pi), minimax atan poly on [0,1], max err ~1e-5 rad
    float ay = fabsf(y), az = fabsf(z);
    float mn = fminf(ay, az), mx = fmaxf(ay, az);
    float a = __fdividef(mn, mx);
    float s = a * a;
    float r = fmaf(fmaf(fmaf(fmaf(0.0208351f, s, -0.0851330f),
                             s, 0.1801410f),
                        s, -0.3302995f),
                   s, 0.9998660f) * a;
    if (az > ay) r = 1.5707963267948966f - r;
    if (y < 0.0f) r = 3.14159265358979323f - r;
    r = (z < 0.0f) ? -r : r;
    return r * 57.295779513082323f;
}

static __device__ __forceinline__ void point_op(float x, float y, float z,
                                                float& o0, float& o1) {
    float cx = fminf(fmaxf(x, -1.0f), 1.0f);
    o0 = fmaf(cx, -90.0f, -90.0f);   // -(cx+1)*90
    o1 = fast_atan2_deg(z, y);
}

__global__ void __launch_bounds__(TPB) cil_kernel(const float4* __restrict__ in4,
                                                  float4* __restrict__ out4,
                                                  int n_quads) {
    int t = blockIdx.x * TPB + threadIdx.x;
    if (t >= n_quads) return;

    // 4 points = 12 floats in = 3x LDG.128 ; 8 floats out = 2x STG.128
    float4 a = in4[3 * t + 0];  // x0 y0 z0 x1
    float4 b = in4[3 * t + 1];  // y1 z1 x2 y2
    float4 c = in4[3 * t + 2];  // z2 x3 y3 z3

    float4 o0, o1;
    point_op(a.x, a.y, a.z, o0.x, o0.y);  // p0
    point_op(a.w, b.x, b.y, o0.z, o0.w);  // p1
    point_op(b.z, b.w, c.x, o1.x, o1.y);  // p2
    point_op(c.y, c.z, c.w, o1.z, o1.w);  // p3

    out4[2 * t + 0] = o0;
    out4[2 * t + 1] = o1;
}

extern "C" void kernel_launch(void* const* d_in, const int* in_sizes, int n_in,
                              void* d_out, int out_size) {
    const float4* in4 = (const float4*)d_in[0];
    float4* out4 = (float4*)d_out;

    int n_points = in_sizes[0] / 3;      // 8,388,608
    int n_quads = n_points / 4;          // 2,097,152 (exact: divisible)

    int blocks = (n_quads + TPB - 1) / TPB;   // 8192
    cil_kernel<<<blocks, TPB>>>(in4, out4, n_quads);
}